// round 5
// baseline (speedup 1.0000x reference)
#include <cuda_runtime.h>
#include <cuda_bf16.h>
#include <math.h>
#include <stdint.h>

// ---------------- problem constants ----------------------------------------
#define B_ 1024
#define T_ 64
#define D_ 512
#define HD_ 512
#define L_ 3
#define NG 2048          // 4*HD gate columns (gate-interleaved)
#define KK 1024          // D + HD fused K
#define FN_ 64
#define ATT 63

// ---------------- device scratch -------------------------------------------
__device__ __align__(16) __nv_bfloat16 g_Whi[(size_t)L_ * NG * KK];   // [l][n][k]
__device__ __align__(16) __nv_bfloat16 g_Wlo[(size_t)L_ * NG * KK];
__device__ __align__(16) __nv_bfloat16 g_xhi[(size_t)T_ * B_ * D_];   // [t][b][d]
__device__ __align__(16) __nv_bfloat16 g_xlo[(size_t)T_ * B_ * D_];
__device__ __align__(16) __nv_bfloat16 g_hhi[(size_t)2 * L_ * B_ * HD_];
__device__ __align__(16) __nv_bfloat16 g_hlo[(size_t)2 * L_ * B_ * HD_];
__device__ float g_c[(size_t)L_ * B_ * HD_];
__device__ __align__(16) float g_bias[L_ * NG];
__device__ float g_ys[(size_t)T_ * B_ * HD_];
__device__ float g_effw[577];

// ---------------- small asm helpers ----------------------------------------
__device__ __forceinline__ uint32_t smem_u32(const void* p) {
    uint32_t a;
    asm("{ .reg .u64 t; cvta.to.shared.u64 t, %1; cvt.u32.u64 %0, t; }" : "=r"(a) : "l"(p));
    return a;
}
__device__ __forceinline__ void cp16(uint32_t dst, const void* src) {
    asm volatile("cp.async.cg.shared.global [%0], [%1], 16;" :: "r"(dst), "l"(src));
}
__device__ __forceinline__ void cp_commit() { asm volatile("cp.async.commit_group;"); }
__device__ __forceinline__ void cp_wait1() { asm volatile("cp.async.wait_group 1;" ::: "memory"); }
__device__ __forceinline__ void cp_wait0() { asm volatile("cp.async.wait_group 0;" ::: "memory"); }

__device__ __forceinline__ void ldsm4(uint32_t* r, uint32_t addr) {
    asm volatile("ldmatrix.sync.aligned.m8n8.x4.shared.b16 {%0,%1,%2,%3}, [%4];"
                 : "=r"(r[0]), "=r"(r[1]), "=r"(r[2]), "=r"(r[3]) : "r"(addr));
}
__device__ __forceinline__ void mma16816(float* c, const uint32_t* a, const uint32_t* b) {
    asm volatile("mma.sync.aligned.m16n8k16.row.col.f32.bf16.bf16.f32 "
                 "{%0,%1,%2,%3}, {%4,%5,%6,%7}, {%8,%9}, {%0,%1,%2,%3};"
                 : "+f"(c[0]), "+f"(c[1]), "+f"(c[2]), "+f"(c[3])
                 : "r"(a[0]), "r"(a[1]), "r"(a[2]), "r"(a[3]), "r"(b[0]), "r"(b[1]));
}
__device__ __forceinline__ float sigf(float x) { return 1.f / (1.f + expf(-x)); }

// ---------------- prep kernels ---------------------------------------------
__global__ void prep_w_kernel(const float* __restrict__ W_ih, const float* __restrict__ W_hh,
                              const float* __restrict__ b_ih, const float* __restrict__ b_hh) {
    size_t idx = (size_t)blockIdx.x * blockDim.x + threadIdx.x;
    const size_t total = (size_t)L_ * NG * KK;
    if (idx < total) {
        int l = (int)(idx / ((size_t)NG * KK));
        size_t r = idx % ((size_t)NG * KK);
        int n = (int)(r / KK), k = (int)(r % KK);
        int oc = (n & 3) * HD_ + (n >> 2);
        float v = (k < D_) ? W_ih[((size_t)l * NG + oc) * D_ + k]
                           : W_hh[((size_t)l * NG + oc) * HD_ + (k - D_)];
        __nv_bfloat16 hi = __float2bfloat16(v);
        g_Whi[idx] = hi;
        g_Wlo[idx] = __float2bfloat16(v - __bfloat162float(hi));
    }
    if (idx < (size_t)L_ * NG) {
        int l = (int)(idx / NG), n = (int)(idx % NG);
        int oc = (n & 3) * HD_ + (n >> 2);
        g_bias[idx] = b_ih[(size_t)l * NG + oc] + b_hh[(size_t)l * NG + oc];
    }
}

// merged: x split + state zero + folded output vector  (keeps launch count low
// so the ncu -s 5 -c 1 capture lands on a 3-cell lstm diagonal)
__global__ void prep_misc_kernel(const float* __restrict__ x,
                                 const float* __restrict__ lin2_W, const float* __restrict__ lin2_b,
                                 const float* __restrict__ out_W, const float* __restrict__ out_b) {
    size_t idx = (size_t)blockIdx.x * blockDim.x + threadIdx.x;
    const size_t totx = (size_t)T_ * B_ * D_;
    if (idx < totx) {
        int t = (int)(idx / ((size_t)B_ * D_));
        size_t r = idx % ((size_t)B_ * D_);
        int b = (int)(r / D_), d = (int)(r % D_);
        float v = x[((size_t)b * T_ + t) * D_ + d];
        __nv_bfloat16 hi = __float2bfloat16(v);
        g_xhi[idx] = hi;
        g_xlo[idx] = __float2bfloat16(v - __bfloat162float(hi));
    }
    const size_t nh = (size_t)2 * L_ * B_ * HD_;
    if (idx < nh) { g_hhi[idx] = __float2bfloat16(0.f); g_hlo[idx] = __float2bfloat16(0.f); }
    if (idx < (size_t)L_ * B_ * HD_) g_c[idx] = 0.f;
    if (idx < 576) {
        float a = 0.f;
        for (int j = 0; j < HD_; j++) a += out_W[j] * lin2_W[(size_t)j * 576 + idx];
        g_effw[idx] = a;
    } else if (idx == 576) {
        float a = out_b[0];
        for (int j = 0; j < HD_; j++) a += out_W[j] * lin2_b[j];
        g_effw[576] = a;
    }
}

// ---------------- mma.sync LSTM step (wavefront cell) -----------------------
// CTA 128(M batch) x 128(N gates), 8 warps (4x2), warp tile 32x64.
// bf16 hi/lo 3-pass (AhBh + AlBh + AhBl) accumulated fp32 in registers.
#define KCH 32
#define NCH (KK / KCH)            // 32 chunks
#define ROWB 80                   // padded smem row bytes (40 bf16)
#define TILE_BYTES (128 * ROWB)   // 10240
#define AH_OFF 0
#define AL_OFF (TILE_BYTES)
#define BH_OFF (2 * TILE_BYTES)
#define BL_OFF (3 * TILE_BYTES)
#define STAGE_BYTES (4 * TILE_BYTES)   // 40960
#define NSTAGE 2
#define DYN_SMEM (NSTAGE * STAGE_BYTES)  // 81920 -> 2 CTAs/SM

__global__ __launch_bounds__(256, 2)
void lstm_step_mma(int diag, int lmin) {
    extern __shared__ __align__(128) char dynsm[];
    const uint32_t smb = smem_u32(dynsm);

    const int tid  = threadIdx.x;
    const int lane = tid & 31;
    const int wid  = tid >> 5;
    const int wm   = (wid & 3) * 32;        // warp m offset in CTA tile
    const int wn   = (wid >> 2) * 64;       // warp n offset
    const int l = lmin + (int)blockIdx.z;
    const int t = diag - l;
    const int mBase = (int)blockIdx.y * 128;
    const int nBase = (int)blockIdx.x * 128;
    const int cur = t & 1, nxt = cur ^ 1;

    // operand bases
    const __nv_bfloat16 *A0h, *A0l;
    if (l == 0) {
        size_t o = (size_t)t * B_ * D_;
        A0h = g_xhi + o; A0l = g_xlo + o;
    } else {
        size_t o = (size_t)(nxt * L_ + (l - 1)) * B_ * HD_;
        A0h = g_hhi + o; A0l = g_hlo + o;
    }
    size_t o1 = (size_t)(cur * L_ + l) * B_ * HD_;
    const __nv_bfloat16 *A1h = g_hhi + o1, *A1l = g_hlo + o1;
    const __nv_bfloat16 *Wh = g_Whi + (size_t)l * NG * KK;
    const __nv_bfloat16 *Wl = g_Wlo + (size_t)l * NG * KK;

    // ---- chunk loader ------------------------------------------------------
    auto load_chunk = [&](int c) {
        const int k0 = c * KCH;
        const __nv_bfloat16 *ah = (k0 < D_) ? A0h + k0 : A1h + (k0 - D_);
        const __nv_bfloat16 *al = (k0 < D_) ? A0l + k0 : A1l + (k0 - D_);
        const uint32_t sb = smb + (c & 1) * STAGE_BYTES;
        for (int i = tid; i < 512; i += 256) {
            int row = i >> 2, ch = i & 3;                 // 128 rows x 4 x 16B
            uint32_t so = (uint32_t)(row * ROWB + ch * 16);
            size_t ga = (size_t)(mBase + row) * 512 + ch * 8;
            size_t gb = (size_t)(nBase + row) * (size_t)KK + k0 + ch * 8;
            cp16(sb + AH_OFF + so, ah + ga);
            cp16(sb + AL_OFF + so, al + ga);
            cp16(sb + BH_OFF + so, Wh + gb);
            cp16(sb + BL_OFF + so, Wl + gb);
        }
        cp_commit();
    };

    float acc[2][8][4];
#pragma unroll
    for (int i = 0; i < 2; i++)
#pragma unroll
        for (int j = 0; j < 8; j++)
#pragma unroll
            for (int q = 0; q < 4; q++) acc[i][j][q] = 0.f;

    // ldmatrix per-lane offsets (within a tile)
    const uint32_t a_off = (uint32_t)((wm + (lane & 15)) * ROWB + (lane >> 4) * 16);
    const uint32_t b_row = (uint32_t)(wn + (lane & 7) + ((lane >> 4) << 3));
    const uint32_t b_off = b_row * ROWB + (((lane >> 3) & 1) << 4);

    load_chunk(0);
    load_chunk(1);

    for (int c = 0; c < NCH; c++) {
        if (c + 1 < NCH) cp_wait1(); else cp_wait0();
        __syncthreads();
        const uint32_t sb = smb + (c & 1) * STAGE_BYTES;

#pragma unroll
        for (int kk = 0; kk < 2; kk++) {
            const uint32_t kofs = (uint32_t)(kk * 32);    // 16 bf16 = 32B
            uint32_t a_hi[2][4], a_lo[2][4];
#pragma unroll
            for (int mt = 0; mt < 2; mt++) {
                uint32_t ad = sb + a_off + (uint32_t)(mt * 16 * ROWB) + kofs;
                ldsm4(a_hi[mt], ad + AH_OFF);
                ldsm4(a_lo[mt], ad + AL_OFF);
            }
            // b_hi passes first (keeps b_hi/b_lo live ranges disjoint -> fits 128 regs)
            {
                uint32_t b_hi[8][2];
#pragma unroll
                for (int g = 0; g < 4; g++) {
                    uint32_t r[4];
                    ldsm4(r, sb + b_off + (uint32_t)(g * 16 * ROWB) + kofs + BH_OFF);
                    b_hi[2 * g][0] = r[0]; b_hi[2 * g][1] = r[1];
                    b_hi[2 * g + 1][0] = r[2]; b_hi[2 * g + 1][1] = r[3];
                }
#pragma unroll
                for (int mt = 0; mt < 2; mt++)
#pragma unroll
                    for (int nt = 0; nt < 8; nt++) mma16816(acc[mt][nt], a_hi[mt], b_hi[nt]);
#pragma unroll
                for (int mt = 0; mt < 2; mt++)
#pragma unroll
                    for (int nt = 0; nt < 8; nt++) mma16816(acc[mt][nt], a_lo[mt], b_hi[nt]);
            }
            {
                uint32_t b_lo[8][2];
#pragma unroll
                for (int g = 0; g < 4; g++) {
                    uint32_t r[4];
                    ldsm4(r, sb + b_off + (uint32_t)(g * 16 * ROWB) + kofs + BL_OFF);
                    b_lo[2 * g][0] = r[0]; b_lo[2 * g][1] = r[1];
                    b_lo[2 * g + 1][0] = r[2]; b_lo[2 * g + 1][1] = r[3];
                }
#pragma unroll
                for (int mt = 0; mt < 2; mt++)
#pragma unroll
                    for (int nt = 0; nt < 8; nt++) mma16816(acc[mt][nt], a_hi[mt], b_lo[nt]);
            }
        }
        __syncthreads();                     // stage (c&1) fully consumed
        if (c + 2 < NCH) load_chunk(c + 2);  // safe: overwrites consumed stage
    }

    // ---- fused LSTM-cell epilogue -----------------------------------------
    const int q = lane & 3;
    const bool active = (q & 1) == 0;
    float* cbase = g_c + (size_t)l * B_ * HD_;
    __nv_bfloat16* hh = g_hhi + (size_t)(nxt * L_ + l) * B_ * HD_;
    __nv_bfloat16* hl = g_hlo + (size_t)(nxt * L_ + l) * B_ * HD_;
    float* ys = (l == 2) ? (g_ys + (size_t)t * B_ * HD_) : nullptr;

#pragma unroll
    for (int mt = 0; mt < 2; mt++) {
#pragma unroll
        for (int nt = 0; nt < 8; nt++) {
            float* cc = acc[mt][nt];
            float p0 = __shfl_xor_sync(0xffffffffu, cc[0], 1);
            float p1 = __shfl_xor_sync(0xffffffffu, cc[1], 1);
            float p2 = __shfl_xor_sync(0xffffffffu, cc[2], 1);
            float p3 = __shfl_xor_sync(0xffffffffu, cc[3], 1);
            if (active) {
                int n0 = nBase + wn + nt * 8 + q * 2;     // multiple of 4
                int j = n0 >> 2;
                const float4 bs = *(const float4*)&g_bias[l * NG + n0];
                int r0 = mBase + wm + mt * 16 + (lane >> 2);
#pragma unroll
                for (int rg = 0; rg < 2; rg++) {
                    int row = r0 + rg * 8;
                    float gi = (rg ? cc[2] : cc[0]) + bs.x;
                    float gf = (rg ? cc[3] : cc[1]) + bs.y;
                    float gg = (rg ? p2 : p0) + bs.z;
                    float go = (rg ? p3 : p1) + bs.w;
                    size_t off = (size_t)row * HD_ + j;
                    float cold = cbase[off];
                    float cn = sigf(gf) * cold + sigf(gi) * tanhf(gg);
                    float hn = sigf(go) * tanhf(cn);
                    cbase[off] = cn;
                    __nv_bfloat16 hi = __float2bfloat16(hn);
                    hh[off] = hi;
                    hl[off] = __float2bfloat16(hn - __bfloat162float(hi));
                    if (ys) ys[off] = hn;
                }
            }
        }
    }
}

// ---------------- attention / TPA head --------------------------------------
#define HEAD_SMEM_FLOATS (32768 + 8064 + 4032 + 512 + 64 + 512 + 64 + 256)

__global__ __launch_bounds__(256)
void head_kernel(const float* __restrict__ conv_W, const float* __restrict__ conv_b,
                 const float* __restrict__ lin1_W, const float* __restrict__ lin1_b,
                 float* __restrict__ out) {
    extern __shared__ float sm[];
    float* conv_s  = sm;
    float* Hblk    = conv_s + 32768;
    float* kW_s    = Hblk + 8064;
    float* htt_s   = kW_s + 4032;
    float* w_s     = htt_s + 512;
    float* alpha_s = w_s + 64;
    float* v_s     = alpha_s + 512;
    float* red_s   = v_s + 64;

    const int b = blockIdx.x;
    const int tid = threadIdx.x;
    const int lane = tid & 31;
    const int warp = tid >> 5;

    for (int i = tid; i < FN_ * ATT; i += 256) kW_s[i] = conv_W[i];
    for (int i = tid; i < HD_; i += 256)
        htt_s[i] = g_ys[(size_t)(T_ - 1) * B_ * HD_ + (size_t)b * HD_ + i];
    __syncthreads();

    for (int qq = 0; qq < 8; qq++) {
        int qi = warp * 8 + qq;
        float p = 0.f;
        for (int k = lane; k < HD_; k += 32) p += htt_s[k] * lin1_W[(size_t)qi * HD_ + k];
#pragma unroll
        for (int o = 16; o; o >>= 1) p += __shfl_xor_sync(0xffffffffu, p, o);
        if (lane == 0) w_s[qi] = p + lin1_b[qi];
    }

    for (int fb = 0; fb < 4; fb++) {
        int f0 = fb * 128;
        for (int i = tid; i < ATT * 128; i += 256) {
            int tt = i >> 7, fi = i & 127;
            float v = g_ys[(size_t)tt * B_ * HD_ + (size_t)b * HD_ + f0 + fi];
            Hblk[i] = v > 0.f ? v : 0.f;
        }
        __syncthreads();
        int fi = tid & 127;
        int c0 = tid >> 7;
        for (int c = c0; c < FN_; c += 2) {
            float acc = conv_b[c];
            const float* kwr = &kW_s[c * ATT];
            for (int tt = 0; tt < ATT; tt++) acc += kwr[tt] * Hblk[tt * 128 + fi];
            conv_s[(c << 9) + f0 + fi] = acc > 0.f ? acc : 0.f;
        }
        __syncthreads();
    }

    for (int p = warp; p < 512; p += 8) {
        float a = conv_s[p * 64 + lane] * w_s[lane]
                + conv_s[p * 64 + 32 + lane] * w_s[32 + lane];
#pragma unroll
        for (int o = 16; o; o >>= 1) a += __shfl_xor_sync(0xffffffffu, a, o);
        if (lane == 0) alpha_s[p] = 1.f / (1.f + expf(-a));
    }
    __syncthreads();

    {
        int qn = tid & 63, part = tid >> 6;
        float a = 0.f;
        for (int p = part; p < 512; p += 4) a += alpha_s[p] * conv_s[p * 64 + qn];
        red_s[tid] = a;
    }
    __syncthreads();
    if (tid < 64) v_s[tid] = red_s[tid] + red_s[64 + tid] + red_s[128 + tid] + red_s[192 + tid];
    __syncthreads();

    float a = 0.f;
    for (int k = tid; k < HD_; k += 256) a += htt_s[k] * g_effw[k];
    if (tid < 64) a += v_s[tid] * g_effw[HD_ + tid];
#pragma unroll
    for (int o = 16; o; o >>= 1) a += __shfl_xor_sync(0xffffffffu, a, o);
    if (lane == 0) red_s[warp] = a;
    __syncthreads();
    if (tid == 0) {
        float tot = g_effw[576];
        for (int i = 0; i < 8; i++) tot += red_s[i];
        out[b] = tot;
    }
}

// ---------------- launch ----------------------------------------------------
extern "C" void kernel_launch(void* const* d_in, const int* in_sizes, int n_in,
                              void* d_out, int out_size) {
    const float* x      = (const float*)d_in[0];
    const float* W_ih   = (const float*)d_in[1];
    const float* W_hh   = (const float*)d_in[2];
    const float* b_ih   = (const float*)d_in[3];
    const float* b_hh   = (const float*)d_in[4];
    const float* conv_W = (const float*)d_in[5];
    const float* conv_b = (const float*)d_in[6];
    const float* lin1_W = (const float*)d_in[7];
    const float* lin1_b = (const float*)d_in[8];
    const float* lin2_W = (const float*)d_in[9];
    const float* lin2_b = (const float*)d_in[10];
    const float* out_W  = (const float*)d_in[11];
    const float* out_b  = (const float*)d_in[12];
    float* out = (float*)d_out;

    {   // prep (2 launches)
        size_t tw = (size_t)L_ * NG * KK;
        prep_w_kernel<<<(unsigned)((tw + 255) / 256), 256>>>(W_ih, W_hh, b_ih, b_hh);
        size_t tx = (size_t)T_ * B_ * D_;
        prep_misc_kernel<<<(unsigned)((tx + 255) / 256), 256>>>(x, lin2_W, lin2_b, out_W, out_b);
    }

    // wavefront recurrence over diagonals d = t + l
    cudaFuncSetAttribute(lstm_step_mma, cudaFuncAttributeMaxDynamicSharedMemorySize, DYN_SMEM);
    for (int d = 0; d < T_ + L_ - 1; d++) {
        int lmin = d - (T_ - 1); if (lmin < 0) lmin = 0;
        int lmax = (d < L_ - 1) ? d : (L_ - 1);
        dim3 grid(NG / 128, B_ / 128, lmax - lmin + 1);   // (16, 8, nc)
        lstm_step_mma<<<grid, 256, DYN_SMEM>>>(d, lmin);
    }

    // head
    cudaFuncSetAttribute(head_kernel, cudaFuncAttributeMaxDynamicSharedMemorySize,
                         HEAD_SMEM_FLOATS * (int)sizeof(float));
    head_kernel<<<B_, 256, HEAD_SMEM_FLOATS * (int)sizeof(float)>>>(
        conv_W, conv_b, lin1_W, lin1_b, out);
}

// round 6
// speedup vs baseline: 1.2118x; 1.2118x over previous
#include <cuda_runtime.h>
#include <cuda_bf16.h>
#include <math.h>
#include <stdint.h>

// ---------------- problem constants ----------------------------------------
#define B_ 1024
#define T_ 64
#define D_ 512
#define HD_ 512
#define L_ 3
#define NG 2048          // 4*HD gate columns (gate-interleaved)
#define KK 1024          // D + HD fused K
#define FN_ 64
#define ATT 63

// ---------------- device scratch -------------------------------------------
__device__ __align__(16) __nv_bfloat16 g_Whi[(size_t)L_ * NG * KK];   // [l][n][k]
__device__ __align__(16) __nv_bfloat16 g_Wlo[(size_t)L_ * NG * KK];
__device__ __align__(16) __nv_bfloat16 g_xhi[(size_t)T_ * B_ * D_];   // [t][b][d]
__device__ __align__(16) __nv_bfloat16 g_xlo[(size_t)T_ * B_ * D_];
__device__ __align__(16) __nv_bfloat16 g_hhi[(size_t)2 * L_ * B_ * HD_];
__device__ __align__(16) __nv_bfloat16 g_hlo[(size_t)2 * L_ * B_ * HD_];
__device__ float g_c[(size_t)L_ * B_ * HD_];
__device__ __align__(16) float g_bias[L_ * NG];
__device__ float g_ys[(size_t)T_ * B_ * HD_];
__device__ float g_effw[577];

// ---------------- small asm helpers ----------------------------------------
__device__ __forceinline__ uint32_t smem_u32(const void* p) {
    uint32_t a;
    asm("{ .reg .u64 t; cvta.to.shared.u64 t, %1; cvt.u32.u64 %0, t; }" : "=r"(a) : "l"(p));
    return a;
}
__device__ __forceinline__ void cp16(uint32_t dst, const void* src) {
    asm volatile("cp.async.cg.shared.global [%0], [%1], 16;" :: "r"(dst), "l"(src));
}
__device__ __forceinline__ void cp_commit() { asm volatile("cp.async.commit_group;"); }
__device__ __forceinline__ void cp_wait1() { asm volatile("cp.async.wait_group 1;" ::: "memory"); }
__device__ __forceinline__ void cp_wait0() { asm volatile("cp.async.wait_group 0;" ::: "memory"); }

__device__ __forceinline__ void ldsm4(uint32_t* r, uint32_t addr) {
    asm volatile("ldmatrix.sync.aligned.m8n8.x4.shared.b16 {%0,%1,%2,%3}, [%4];"
                 : "=r"(r[0]), "=r"(r[1]), "=r"(r[2]), "=r"(r[3]) : "r"(addr));
}
__device__ __forceinline__ void mma16816(float* c, const uint32_t* a, const uint32_t* b) {
    asm volatile("mma.sync.aligned.m16n8k16.row.col.f32.bf16.bf16.f32 "
                 "{%0,%1,%2,%3}, {%4,%5,%6,%7}, {%8,%9}, {%0,%1,%2,%3};"
                 : "+f"(c[0]), "+f"(c[1]), "+f"(c[2]), "+f"(c[3])
                 : "r"(a[0]), "r"(a[1]), "r"(a[2]), "r"(a[3]), "r"(b[0]), "r"(b[1]));
}
__device__ __forceinline__ float sigf(float x) { return 1.f / (1.f + expf(-x)); }

// ---------------- prep kernels ---------------------------------------------
__global__ void prep_w_kernel(const float* __restrict__ W_ih, const float* __restrict__ W_hh,
                              const float* __restrict__ b_ih, const float* __restrict__ b_hh) {
    size_t idx = (size_t)blockIdx.x * blockDim.x + threadIdx.x;
    const size_t total = (size_t)L_ * NG * KK;
    if (idx < total) {
        int l = (int)(idx / ((size_t)NG * KK));
        size_t r = idx % ((size_t)NG * KK);
        int n = (int)(r / KK), k = (int)(r % KK);
        int oc = (n & 3) * HD_ + (n >> 2);
        float v = (k < D_) ? W_ih[((size_t)l * NG + oc) * D_ + k]
                           : W_hh[((size_t)l * NG + oc) * HD_ + (k - D_)];
        __nv_bfloat16 hi = __float2bfloat16(v);
        g_Whi[idx] = hi;
        g_Wlo[idx] = __float2bfloat16(v - __bfloat162float(hi));
    }
    if (idx < (size_t)L_ * NG) {
        int l = (int)(idx / NG), n = (int)(idx % NG);
        int oc = (n & 3) * HD_ + (n >> 2);
        g_bias[idx] = b_ih[(size_t)l * NG + oc] + b_hh[(size_t)l * NG + oc];
    }
}

// merged: x split + state zero + folded output vector
__global__ void prep_misc_kernel(const float* __restrict__ x,
                                 const float* __restrict__ lin2_W, const float* __restrict__ lin2_b,
                                 const float* __restrict__ out_W, const float* __restrict__ out_b) {
    size_t idx = (size_t)blockIdx.x * blockDim.x + threadIdx.x;
    const size_t totx = (size_t)T_ * B_ * D_;
    if (idx < totx) {
        int t = (int)(idx / ((size_t)B_ * D_));
        size_t r = idx % ((size_t)B_ * D_);
        int b = (int)(r / D_), d = (int)(r % D_);
        float v = x[((size_t)b * T_ + t) * D_ + d];
        __nv_bfloat16 hi = __float2bfloat16(v);
        g_xhi[idx] = hi;
        g_xlo[idx] = __float2bfloat16(v - __bfloat162float(hi));
    }
    const size_t nh = (size_t)2 * L_ * B_ * HD_;
    if (idx < nh) { g_hhi[idx] = __float2bfloat16(0.f); g_hlo[idx] = __float2bfloat16(0.f); }
    if (idx < (size_t)L_ * B_ * HD_) g_c[idx] = 0.f;
    if (idx < 576) {
        float a = 0.f;
        for (int j = 0; j < HD_; j++) a += out_W[j] * lin2_W[(size_t)j * 576 + idx];
        g_effw[idx] = a;
    } else if (idx == 576) {
        float a = out_b[0];
        for (int j = 0; j < HD_; j++) a += out_W[j] * lin2_b[j];
        g_effw[576] = a;
    }
}

// ---------------- mma.sync LSTM step (wavefront cell) -----------------------
// CTA 128(M batch) x 128(N gates), 8 warps (4x2), warp tile 32x64.
// bf16 hi/lo 3-pass (AhBh + AlBh + AhBl), fp32 register accumulators.
#define KCH 64
#define NCH (KK / KCH)            // 16 chunks
#define ROWB 144                  // 128B payload + 16B pad (conflict-free ldmatrix)
#define TILE_BYTES (128 * ROWB)   // 18432
#define AH_OFF 0
#define AL_OFF (TILE_BYTES)
#define BH_OFF (2 * TILE_BYTES)
#define BL_OFF (3 * TILE_BYTES)
#define STAGE_BYTES (4 * TILE_BYTES)   // 73728
#define NSTAGE 3
#define DYN_SMEM (NSTAGE * STAGE_BYTES)  // 221184 (1 CTA/SM)

__global__ __launch_bounds__(256, 1)
void lstm_step_mma(int diag, int lmin) {
    extern __shared__ __align__(128) char dynsm[];
    const uint32_t smb = smem_u32(dynsm);

    const int tid  = threadIdx.x;
    const int lane = tid & 31;
    const int wid  = tid >> 5;
    const int wm   = (wid & 3) * 32;        // warp m offset
    const int wn   = (wid >> 2) * 64;       // warp n offset
    const int l = lmin + (int)blockIdx.z;
    const int t = diag - l;
    const int mBase = (int)blockIdx.y * 128;
    const int nBase = (int)blockIdx.x * 128;
    const int cur = t & 1, nxt = cur ^ 1;

    // operand bases
    const __nv_bfloat16 *A0h, *A0l;
    if (l == 0) {
        size_t o = (size_t)t * B_ * D_;
        A0h = g_xhi + o; A0l = g_xlo + o;
    } else {
        size_t o = (size_t)(nxt * L_ + (l - 1)) * B_ * HD_;
        A0h = g_hhi + o; A0l = g_hlo + o;
    }
    size_t o1 = (size_t)(cur * L_ + l) * B_ * HD_;
    const __nv_bfloat16 *A1h = g_hhi + o1, *A1l = g_hlo + o1;
    const __nv_bfloat16 *Wh = g_Whi + (size_t)l * NG * KK;
    const __nv_bfloat16 *Wl = g_Wlo + (size_t)l * NG * KK;

    // ---- chunk loader: 72KB per chunk via cp.async --------------------------
    // chunk = KCH(64) k-columns; A rows stride 512, B rows stride 1024.
    auto load_chunk = [&](int c) {
        const int k0 = c * KCH;                      // multiple of 64 -> never splits A0/A1
        const __nv_bfloat16 *ah = (k0 < D_) ? A0h + k0 : A1h + (k0 - D_);
        const __nv_bfloat16 *al = (k0 < D_) ? A0l + k0 : A1l + (k0 - D_);
        const uint32_t sb = smb + (c % NSTAGE) * STAGE_BYTES;
        for (int i = tid; i < 1024; i += 256) {      // 128 rows x 8 x 16B per operand
            int row = i >> 3, ch = i & 7;
            uint32_t so = (uint32_t)(row * ROWB + ch * 16);
            size_t ga = (size_t)(mBase + row) * 512 + ch * 8;
            size_t gb = (size_t)(nBase + row) * (size_t)KK + k0 + ch * 8;
            cp16(sb + AH_OFF + so, ah + ga);
            cp16(sb + AL_OFF + so, al + ga);
            cp16(sb + BH_OFF + so, Wh + gb);
            cp16(sb + BL_OFF + so, Wl + gb);
        }
        cp_commit();
    };

    float acc[2][8][4];
#pragma unroll
    for (int i = 0; i < 2; i++)
#pragma unroll
        for (int j = 0; j < 8; j++)
#pragma unroll
            for (int q = 0; q < 4; q++) acc[i][j][q] = 0.f;

    // ldmatrix per-lane offsets (within a tile)
    const uint32_t a_off = (uint32_t)((wm + (lane & 15)) * ROWB + (lane >> 4) * 16);
    const uint32_t b_row = (uint32_t)(wn + (lane & 7) + ((lane >> 4) << 3));
    const uint32_t b_off = b_row * ROWB + (((lane >> 3) & 1) << 4);

    load_chunk(0);
    load_chunk(1);

    for (int c = 0; c < NCH; c++) {
        if (c + 1 < NCH) cp_wait1(); else cp_wait0();
        __syncthreads();
        const uint32_t sb = smb + (c % NSTAGE) * STAGE_BYTES;

#pragma unroll
        for (int kk = 0; kk < 4; kk++) {             // 4 x k16 per 64-k chunk
            const uint32_t kofs = (uint32_t)(kk * 32);
            uint32_t a_hi[2][4], a_lo[2][4];
#pragma unroll
            for (int mt = 0; mt < 2; mt++) {
                uint32_t ad = sb + a_off + (uint32_t)(mt * 16 * ROWB) + kofs;
                ldsm4(a_hi[mt], ad + AH_OFF);
                ldsm4(a_lo[mt], ad + AL_OFF);
            }
            uint32_t b_hi[8][2], b_lo[8][2];
#pragma unroll
            for (int g = 0; g < 4; g++) {
                uint32_t bd = sb + b_off + (uint32_t)(g * 16 * ROWB) + kofs;
                uint32_t r[4];
                ldsm4(r, bd + BH_OFF);
                b_hi[2 * g][0] = r[0]; b_hi[2 * g][1] = r[1];
                b_hi[2 * g + 1][0] = r[2]; b_hi[2 * g + 1][1] = r[3];
                ldsm4(r, bd + BL_OFF);
                b_lo[2 * g][0] = r[0]; b_lo[2 * g][1] = r[1];
                b_lo[2 * g + 1][0] = r[2]; b_lo[2 * g + 1][1] = r[3];
            }
#pragma unroll
            for (int mt = 0; mt < 2; mt++)
#pragma unroll
                for (int nt = 0; nt < 8; nt++) mma16816(acc[mt][nt], a_hi[mt], b_hi[nt]);
#pragma unroll
            for (int mt = 0; mt < 2; mt++)
#pragma unroll
                for (int nt = 0; nt < 8; nt++) mma16816(acc[mt][nt], a_lo[mt], b_hi[nt]);
#pragma unroll
            for (int mt = 0; mt < 2; mt++)
#pragma unroll
                for (int nt = 0; nt < 8; nt++) mma16816(acc[mt][nt], a_hi[mt], b_lo[nt]);
        }
        // stage (c+2)%NSTAGE was fully consumed at chunk c-1; barrier above protects it
        if (c + 2 < NCH) load_chunk(c + 2);
    }

    // ---- fused LSTM-cell epilogue -----------------------------------------
    const int q = lane & 3;
    const bool active = (q & 1) == 0;
    float* cbase = g_c + (size_t)l * B_ * HD_;
    __nv_bfloat16* hh = g_hhi + (size_t)(nxt * L_ + l) * B_ * HD_;
    __nv_bfloat16* hl = g_hlo + (size_t)(nxt * L_ + l) * B_ * HD_;
    float* ys = (l == 2) ? (g_ys + (size_t)t * B_ * HD_) : nullptr;

#pragma unroll
    for (int mt = 0; mt < 2; mt++) {
#pragma unroll
        for (int nt = 0; nt < 8; nt++) {
            float* cc = acc[mt][nt];
            float p0 = __shfl_xor_sync(0xffffffffu, cc[0], 1);
            float p1 = __shfl_xor_sync(0xffffffffu, cc[1], 1);
            float p2 = __shfl_xor_sync(0xffffffffu, cc[2], 1);
            float p3 = __shfl_xor_sync(0xffffffffu, cc[3], 1);
            if (active) {
                int n0 = nBase + wn + nt * 8 + q * 2;     // multiple of 4
                int j = n0 >> 2;
                const float4 bs = *(const float4*)&g_bias[l * NG + n0];
                int r0 = mBase + wm + mt * 16 + (lane >> 2);
#pragma unroll
                for (int rg = 0; rg < 2; rg++) {
                    int row = r0 + rg * 8;
                    float gi = (rg ? cc[2] : cc[0]) + bs.x;
                    float gf = (rg ? cc[3] : cc[1]) + bs.y;
                    float gg = (rg ? p2 : p0) + bs.z;
                    float go = (rg ? p3 : p1) + bs.w;
                    size_t off = (size_t)row * HD_ + j;
                    float cold = cbase[off];
                    float cn = sigf(gf) * cold + sigf(gi) * tanhf(gg);
                    float hn = sigf(go) * tanhf(cn);
                    cbase[off] = cn;
                    __nv_bfloat16 hi = __float2bfloat16(hn);
                    hh[off] = hi;
                    hl[off] = __float2bfloat16(hn - __bfloat162float(hi));
                    if (ys) ys[off] = hn;
                }
            }
        }
    }
}

// ---------------- attention / TPA head --------------------------------------
#define HEAD_SMEM_FLOATS (32768 + 8064 + 4032 + 512 + 64 + 512 + 64 + 256)

__global__ __launch_bounds__(256)
void head_kernel(const float* __restrict__ conv_W, const float* __restrict__ conv_b,
                 const float* __restrict__ lin1_W, const float* __restrict__ lin1_b,
                 float* __restrict__ out) {
    extern __shared__ float sm[];
    float* conv_s  = sm;
    float* Hblk    = conv_s + 32768;
    float* kW_s    = Hblk + 8064;
    float* htt_s   = kW_s + 4032;
    float* w_s     = htt_s + 512;
    float* alpha_s = w_s + 64;
    float* v_s     = alpha_s + 512;
    float* red_s   = v_s + 64;

    const int b = blockIdx.x;
    const int tid = threadIdx.x;
    const int lane = tid & 31;
    const int warp = tid >> 5;

    for (int i = tid; i < FN_ * ATT; i += 256) kW_s[i] = conv_W[i];
    for (int i = tid; i < HD_; i += 256)
        htt_s[i] = g_ys[(size_t)(T_ - 1) * B_ * HD_ + (size_t)b * HD_ + i];
    __syncthreads();

    for (int qq = 0; qq < 8; qq++) {
        int qi = warp * 8 + qq;
        float p = 0.f;
        for (int k = lane; k < HD_; k += 32) p += htt_s[k] * lin1_W[(size_t)qi * HD_ + k];
#pragma unroll
        for (int o = 16; o; o >>= 1) p += __shfl_xor_sync(0xffffffffu, p, o);
        if (lane == 0) w_s[qi] = p + lin1_b[qi];
    }

    for (int fb = 0; fb < 4; fb++) {
        int f0 = fb * 128;
        for (int i = tid; i < ATT * 128; i += 256) {
            int tt = i >> 7, fi = i & 127;
            float v = g_ys[(size_t)tt * B_ * HD_ + (size_t)b * HD_ + f0 + fi];
            Hblk[i] = v > 0.f ? v : 0.f;
        }
        __syncthreads();
        int fi = tid & 127;
        int c0 = tid >> 7;
        for (int c = c0; c < FN_; c += 2) {
            float acc = conv_b[c];
            const float* kwr = &kW_s[c * ATT];
            for (int tt = 0; tt < ATT; tt++) acc += kwr[tt] * Hblk[tt * 128 + fi];
            conv_s[(c << 9) + f0 + fi] = acc > 0.f ? acc : 0.f;
        }
        __syncthreads();
    }

    for (int p = warp; p < 512; p += 8) {
        float a = conv_s[p * 64 + lane] * w_s[lane]
                + conv_s[p * 64 + 32 + lane] * w_s[32 + lane];
#pragma unroll
        for (int o = 16; o; o >>= 1) a += __shfl_xor_sync(0xffffffffu, a, o);
        if (lane == 0) alpha_s[p] = 1.f / (1.f + expf(-a));
    }
    __syncthreads();

    {
        int qn = tid & 63, part = tid >> 6;
        float a = 0.f;
        for (int p = part; p < 512; p += 4) a += alpha_s[p] * conv_s[p * 64 + qn];
        red_s[tid] = a;
    }
    __syncthreads();
    if (tid < 64) v_s[tid] = red_s[tid] + red_s[64 + tid] + red_s[128 + tid] + red_s[192 + tid];
    __syncthreads();

    float a = 0.f;
    for (int k = tid; k < HD_; k += 256) a += htt_s[k] * g_effw[k];
    if (tid < 64) a += v_s[tid] * g_effw[HD_ + tid];
#pragma unroll
    for (int o = 16; o; o >>= 1) a += __shfl_xor_sync(0xffffffffu, a, o);
    if (lane == 0) red_s[warp] = a;
    __syncthreads();
    if (tid == 0) {
        float tot = g_effw[576];
        for (int i = 0; i < 8; i++) tot += red_s[i];
        out[b] = tot;
    }
}

// ---------------- launch ----------------------------------------------------
extern "C" void kernel_launch(void* const* d_in, const int* in_sizes, int n_in,
                              void* d_out, int out_size) {
    const float* x      = (const float*)d_in[0];
    const float* W_ih   = (const float*)d_in[1];
    const float* W_hh   = (const float*)d_in[2];
    const float* b_ih   = (const float*)d_in[3];
    const float* b_hh   = (const float*)d_in[4];
    const float* conv_W = (const float*)d_in[5];
    const float* conv_b = (const float*)d_in[6];
    const float* lin1_W = (const float*)d_in[7];
    const float* lin1_b = (const float*)d_in[8];
    const float* lin2_W = (const float*)d_in[9];
    const float* lin2_b = (const float*)d_in[10];
    const float* out_W  = (const float*)d_in[11];
    const float* out_b  = (const float*)d_in[12];
    float* out = (float*)d_out;

    {   // prep (2 launches)
        size_t tw = (size_t)L_ * NG * KK;
        prep_w_kernel<<<(unsigned)((tw + 255) / 256), 256>>>(W_ih, W_hh, b_ih, b_hh);
        size_t tx = (size_t)T_ * B_ * D_;
        prep_misc_kernel<<<(unsigned)((tx + 255) / 256), 256>>>(x, lin2_W, lin2_b, out_W, out_b);
    }

    // wavefront recurrence over diagonals d = t + l
    cudaFuncSetAttribute(lstm_step_mma, cudaFuncAttributeMaxDynamicSharedMemorySize, DYN_SMEM);
    for (int d = 0; d < T_ + L_ - 1; d++) {
        int lmin = d - (T_ - 1); if (lmin < 0) lmin = 0;
        int lmax = (d < L_ - 1) ? d : (L_ - 1);
        dim3 grid(NG / 128, B_ / 128, lmax - lmin + 1);   // (16, 8, nc)
        lstm_step_mma<<<grid, 256, DYN_SMEM>>>(d, lmin);
    }

    // head
    cudaFuncSetAttribute(head_kernel, cudaFuncAttributeMaxDynamicSharedMemorySize,
                         HEAD_SMEM_FLOATS * (int)sizeof(float));
    head_kernel<<<B_, 256, HEAD_SMEM_FLOATS * (int)sizeof(float)>>>(
        conv_W, conv_b, lin1_W, lin1_b, out);
}